// round 3
// baseline (speedup 1.0000x reference)
#include <cuda_runtime.h>
#include <cstdint>

#define N_VERTS 262144
#define N_PAIRS 8388608
#define DHAT2 0.0025f
#define EPSF 1e-12f

// Verts cached in shared memory per CTA (224 KB of float2 = 10.9% of table).
#define CACHE_VERTS 28672
#define MAIN_BLOCK 1024
#define MAIN_GRID 148

// Scratch: current coordinates (rest + displacement), fits in L2 (2 MB).
__device__ float2 g_coords[N_VERTS];

// ---------------------------------------------------------------------------
// Kernel A: coords = rest + Uu.reshape(-1,2); also zero the output scalar.
// ---------------------------------------------------------------------------
__global__ void build_coords_kernel(const float* __restrict__ Uu,
                                    const float* __restrict__ rest,
                                    float* __restrict__ out) {
    int i = blockIdx.x * blockDim.x + threadIdx.x;
    if (i < N_VERTS) {
        float2 r = reinterpret_cast<const float2*>(rest)[i];
        float2 u = reinterpret_cast<const float2*>(Uu)[i];
        g_coords[i] = make_float2(r.x + u.x, r.y + u.y);
    }
    if (blockIdx.x == 0 && threadIdx.x == 0) {
        out[0] = 0.0f;  // d_out is poisoned; initialize
    }
}

// ---------------------------------------------------------------------------
// Hybrid gather via generic addressing: one LD.E.64, lanes split between the
// shared-memory crossbar (idx < CACHE_VERTS) and the L1tex path. Cheap select,
// no predication blob, low register cost -> MLP preserved.
// ---------------------------------------------------------------------------
__device__ __forceinline__ float2 gather_coord(const float2* sc, int idx) {
    const float2* p = (idx < CACHE_VERTS) ? (sc + idx) : (g_coords + idx);
    return *p;
}

// ---------------------------------------------------------------------------
// Per-pair barrier term (exact reference math, fp32).
// ---------------------------------------------------------------------------
__device__ __forceinline__ float pair_barrier(const float2* sc,
                                              int iv, int ie0, int ie1) {
    float2 p = gather_coord(sc, iv);
    float2 a = gather_coord(sc, ie0);
    float2 b = gather_coord(sc, ie1);

    float abx = b.x - a.x, aby = b.y - a.y;
    float apx = p.x - a.x, apy = p.y - a.y;
    float denom = abx * abx + aby * aby;
    float t = (apx * abx + apy * aby) / fmaxf(denom, EPSF);
    t = fminf(fmaxf(t, 0.0f), 1.0f);
    float dx = apx - t * abx;
    float dy = apy - t * aby;
    float d2 = dx * dx + dy * dy;

    if (d2 < DHAT2) {
        float d2s = fmaxf(d2, EPSF);
        float m = d2s - DHAT2;
        return -(m * m) * logf(d2s / DHAT2);
    }
    return 0.0f;
}

// ---------------------------------------------------------------------------
// Kernel B: persistent CTA per SM; 224 KB smem vertex cache; grid-stride over
// int4 pair groups (12 independent gathers per iteration); block-reduce.
// ---------------------------------------------------------------------------
__global__ void __launch_bounds__(MAIN_BLOCK, 1)
barrier_energy_kernel(const int4* __restrict__ pv4,
                      const int4* __restrict__ pe04,
                      const int4* __restrict__ pe14,
                      float* __restrict__ out) {
    extern __shared__ float2 s_coords[];

    // Fill the smem vertex cache (coalesced from L2-resident g_coords).
    for (int i = threadIdx.x; i < CACHE_VERTS; i += MAIN_BLOCK)
        s_coords[i] = g_coords[i];
    __syncthreads();

    const int n4 = N_PAIRS / 4;
    double acc = 0.0;

    for (int idx = blockIdx.x * MAIN_BLOCK + threadIdx.x; idx < n4;
         idx += MAIN_GRID * MAIN_BLOCK) {
        int4 v  = __ldg(&pv4[idx]);
        int4 e0 = __ldg(&pe04[idx]);
        int4 e1 = __ldg(&pe14[idx]);

        float s = pair_barrier(s_coords, v.x, e0.x, e1.x)
                + pair_barrier(s_coords, v.y, e0.y, e1.y)
                + pair_barrier(s_coords, v.z, e0.z, e1.z)
                + pair_barrier(s_coords, v.w, e0.w, e1.w);
        acc += (double)s;
    }

    // Warp reduction
    #pragma unroll
    for (int off = 16; off > 0; off >>= 1)
        acc += __shfl_xor_sync(0xFFFFFFFFu, acc, off);

    __shared__ double warp_sums[MAIN_BLOCK / 32];
    int lane = threadIdx.x & 31;
    int wid = threadIdx.x >> 5;
    if (lane == 0) warp_sums[wid] = acc;
    __syncthreads();

    if (wid == 0) {
        double vsum = (lane < (MAIN_BLOCK / 32)) ? warp_sums[lane] : 0.0;
        #pragma unroll
        for (int off = 16; off > 0; off >>= 1)
            vsum += __shfl_xor_sync(0xFFFFFFFFu, vsum, off);
        if (lane == 0)
            atomicAdd(out, (float)vsum);
    }
}

// ---------------------------------------------------------------------------
extern "C" void kernel_launch(void* const* d_in, const int* in_sizes, int n_in,
                              void* d_out, int out_size) {
    const float* Uu   = (const float*)d_in[0];
    const float* rest = (const float*)d_in[1];
    const int4* pv  = (const int4*)d_in[2];
    const int4* pe0 = (const int4*)d_in[3];
    const int4* pe1 = (const int4*)d_in[4];
    float* out = (float*)d_out;

    static bool attr_set = false;
    if (!attr_set) {
        cudaFuncSetAttribute(barrier_energy_kernel,
                             cudaFuncAttributeMaxDynamicSharedMemorySize,
                             CACHE_VERTS * sizeof(float2));
        attr_set = true;
    }

    build_coords_kernel<<<(N_VERTS + 255) / 256, 256>>>(Uu, rest, out);
    barrier_energy_kernel<<<MAIN_GRID, MAIN_BLOCK,
                            CACHE_VERTS * sizeof(float2)>>>(pv, pe0, pe1, out);
}

// round 4
// speedup vs baseline: 1.9483x; 1.9483x over previous
#include <cuda_runtime.h>
#include <cstdint>

#define N_VERTS 262144
#define N_PAIRS 8388608
#define DHAT2 0.0025f
#define EPSF 1e-12f

#define MAIN_BLOCK 256
#define MAIN_GRID 2048

// Scratch: current coordinates (rest + displacement), fits in L2 (2 MB).
__device__ float2 g_coords[N_VERTS];

// ---------------------------------------------------------------------------
// Kernel A: coords = rest + Uu.reshape(-1,2); also zero the output scalar.
// ---------------------------------------------------------------------------
__global__ void build_coords_kernel(const float* __restrict__ Uu,
                                    const float* __restrict__ rest,
                                    float* __restrict__ out) {
    int i = blockIdx.x * blockDim.x + threadIdx.x;
    if (i < N_VERTS) {
        float2 r = reinterpret_cast<const float2*>(rest)[i];
        float2 u = reinterpret_cast<const float2*>(Uu)[i];
        g_coords[i] = make_float2(r.x + u.x, r.y + u.y);
    }
    if (blockIdx.x == 0 && threadIdx.x == 0) {
        out[0] = 0.0f;  // d_out is poisoned; initialize
    }
}

// ---------------------------------------------------------------------------
// Per-pair barrier term (reference math, fp32; fast log/div — rel tolerance
// is 1e-3, __logf error ~5e-7).
// ---------------------------------------------------------------------------
__device__ __forceinline__ float pair_barrier(int iv, int ie0, int ie1) {
    float2 p = __ldg(&g_coords[iv]);
    float2 a = __ldg(&g_coords[ie0]);
    float2 b = __ldg(&g_coords[ie1]);

    float abx = b.x - a.x, aby = b.y - a.y;
    float apx = p.x - a.x, apy = p.y - a.y;
    float denom = abx * abx + aby * aby;
    float t = __fdividef(apx * abx + apy * aby, fmaxf(denom, EPSF));
    t = fminf(fmaxf(t, 0.0f), 1.0f);
    float dx = apx - t * abx;
    float dy = apy - t * aby;
    float d2 = dx * dx + dy * dy;

    if (d2 < DHAT2) {
        float d2s = fmaxf(d2, EPSF);
        float m = d2s - DHAT2;
        return -(m * m) * __logf(d2s * (1.0f / DHAT2));
    }
    return 0.0f;
}

__device__ __forceinline__ float group_barrier(int4 v, int4 e0, int4 e1) {
    return pair_barrier(v.x, e0.x, e1.x)
         + pair_barrier(v.y, e0.y, e1.y)
         + pair_barrier(v.z, e0.z, e1.z)
         + pair_barrier(v.w, e0.w, e1.w);
}

// ---------------------------------------------------------------------------
// Kernel B: grid-stride over int4 pair groups, unrolled x2 so each iteration
// has 6 coalesced int4 index loads + 24 independent random gathers in flight.
// ---------------------------------------------------------------------------
__global__ void __launch_bounds__(MAIN_BLOCK)
barrier_energy_kernel(const int4* __restrict__ pv4,
                      const int4* __restrict__ pe04,
                      const int4* __restrict__ pe14,
                      float* __restrict__ out) {
    const int n4 = N_PAIRS / 4;              // 2097152
    const int stride = MAIN_GRID * MAIN_BLOCK; // 524288
    int tid = blockIdx.x * MAIN_BLOCK + threadIdx.x;

    double acc = 0.0;

    // n4 == 4 * stride exactly for this problem; loop handles the general case.
    int idx = tid;
    for (; idx + stride < n4; idx += 2 * stride) {
        int4 v0  = __ldg(&pv4[idx]);
        int4 e00 = __ldg(&pe04[idx]);
        int4 e10 = __ldg(&pe14[idx]);
        int4 v1  = __ldg(&pv4[idx + stride]);
        int4 e01 = __ldg(&pe04[idx + stride]);
        int4 e11 = __ldg(&pe14[idx + stride]);

        float s0 = group_barrier(v0, e00, e10);
        float s1 = group_barrier(v1, e01, e11);
        acc += (double)(s0 + s1);
    }
    if (idx < n4) {
        int4 v  = __ldg(&pv4[idx]);
        int4 e0 = __ldg(&pe04[idx]);
        int4 e1 = __ldg(&pe14[idx]);
        acc += (double)group_barrier(v, e0, e1);
    }

    // Warp reduction
    #pragma unroll
    for (int off = 16; off > 0; off >>= 1)
        acc += __shfl_xor_sync(0xFFFFFFFFu, acc, off);

    __shared__ double warp_sums[MAIN_BLOCK / 32];
    int lane = threadIdx.x & 31;
    int wid = threadIdx.x >> 5;
    if (lane == 0) warp_sums[wid] = acc;
    __syncthreads();

    if (wid == 0) {
        double vsum = (lane < (MAIN_BLOCK / 32)) ? warp_sums[lane] : 0.0;
        #pragma unroll
        for (int off = 4; off > 0; off >>= 1)
            vsum += __shfl_xor_sync(0xFFFFFFFFu, vsum, off);
        if (lane == 0)
            atomicAdd(out, (float)vsum);
    }
}

// ---------------------------------------------------------------------------
extern "C" void kernel_launch(void* const* d_in, const int* in_sizes, int n_in,
                              void* d_out, int out_size) {
    const float* Uu   = (const float*)d_in[0];
    const float* rest = (const float*)d_in[1];
    const int4* pv  = (const int4*)d_in[2];
    const int4* pe0 = (const int4*)d_in[3];
    const int4* pe1 = (const int4*)d_in[4];
    float* out = (float*)d_out;

    build_coords_kernel<<<(N_VERTS + 255) / 256, 256>>>(Uu, rest, out);
    barrier_energy_kernel<<<MAIN_GRID, MAIN_BLOCK>>>(pv, pe0, pe1, out);
}

// round 5
// speedup vs baseline: 1.9530x; 1.0024x over previous
#include <cuda_runtime.h>
#include <cstdint>

#define N_VERTS 262144
#define N_PAIRS 8388608
#define DHAT2 0.0025f
#define EPSF 1e-12f

#define MAIN_BLOCK 256
// Exactly one wave: 148 SMs x 8 resident blocks (256 thr, 32 regs) = 1184.
#define MAIN_GRID 1184

// Scratch: current coordinates (rest + displacement), fits in L2 (2 MB).
__device__ float2 g_coords[N_VERTS];

// ---------------------------------------------------------------------------
// Kernel A: coords = rest + Uu.reshape(-1,2); also zero the output scalar.
// ---------------------------------------------------------------------------
__global__ void build_coords_kernel(const float* __restrict__ Uu,
                                    const float* __restrict__ rest,
                                    float* __restrict__ out) {
    int i = blockIdx.x * blockDim.x + threadIdx.x;
    if (i < N_VERTS) {
        float2 r = reinterpret_cast<const float2*>(rest)[i];
        float2 u = reinterpret_cast<const float2*>(Uu)[i];
        g_coords[i] = make_float2(r.x + u.x, r.y + u.y);
    }
    if (blockIdx.x == 0 && threadIdx.x == 0) {
        out[0] = 0.0f;  // d_out is poisoned; initialize
    }
}

// ---------------------------------------------------------------------------
// Per-pair barrier term (reference math, fp32; fast log/div — rel tolerance
// is 1e-3, __logf error ~5e-7).
// ---------------------------------------------------------------------------
__device__ __forceinline__ float pair_barrier(int iv, int ie0, int ie1) {
    float2 p = __ldg(&g_coords[iv]);
    float2 a = __ldg(&g_coords[ie0]);
    float2 b = __ldg(&g_coords[ie1]);

    float abx = b.x - a.x, aby = b.y - a.y;
    float apx = p.x - a.x, apy = p.y - a.y;
    float denom = abx * abx + aby * aby;
    float t = __fdividef(apx * abx + apy * aby, fmaxf(denom, EPSF));
    t = fminf(fmaxf(t, 0.0f), 1.0f);
    float dx = apx - t * abx;
    float dy = apy - t * aby;
    float d2 = dx * dx + dy * dy;

    if (d2 < DHAT2) {
        float d2s = fmaxf(d2, EPSF);
        float m = d2s - DHAT2;
        return -(m * m) * __logf(d2s * (1.0f / DHAT2));
    }
    return 0.0f;
}

__device__ __forceinline__ float group_barrier(int4 v, int4 e0, int4 e1) {
    return pair_barrier(v.x, e0.x, e1.x)
         + pair_barrier(v.y, e0.y, e1.y)
         + pair_barrier(v.z, e0.z, e1.z)
         + pair_barrier(v.w, e0.w, e1.w);
}

// ---------------------------------------------------------------------------
// Kernel B: single-wave persistent grid-stride over int4 pair groups,
// unrolled x2 (24 independent random gathers in flight per thread).
// ---------------------------------------------------------------------------
__global__ void __launch_bounds__(MAIN_BLOCK)
barrier_energy_kernel(const int4* __restrict__ pv4,
                      const int4* __restrict__ pe04,
                      const int4* __restrict__ pe14,
                      float* __restrict__ out) {
    const int n4 = N_PAIRS / 4;                 // 2097152
    const int stride = MAIN_GRID * MAIN_BLOCK;  // 303104
    int tid = blockIdx.x * MAIN_BLOCK + threadIdx.x;

    double acc = 0.0;

    int idx = tid;
    for (; idx + stride < n4; idx += 2 * stride) {
        int4 v0  = __ldg(&pv4[idx]);
        int4 e00 = __ldg(&pe04[idx]);
        int4 e10 = __ldg(&pe14[idx]);
        int4 v1  = __ldg(&pv4[idx + stride]);
        int4 e01 = __ldg(&pe04[idx + stride]);
        int4 e11 = __ldg(&pe14[idx + stride]);

        float s0 = group_barrier(v0, e00, e10);
        float s1 = group_barrier(v1, e01, e11);
        acc += (double)(s0 + s1);
    }
    if (idx < n4) {
        int4 v  = __ldg(&pv4[idx]);
        int4 e0 = __ldg(&pe04[idx]);
        int4 e1 = __ldg(&pe14[idx]);
        acc += (double)group_barrier(v, e0, e1);
    }

    // Warp reduction
    #pragma unroll
    for (int off = 16; off > 0; off >>= 1)
        acc += __shfl_xor_sync(0xFFFFFFFFu, acc, off);

    __shared__ double warp_sums[MAIN_BLOCK / 32];
    int lane = threadIdx.x & 31;
    int wid = threadIdx.x >> 5;
    if (lane == 0) warp_sums[wid] = acc;
    __syncthreads();

    if (wid == 0) {
        double vsum = (lane < (MAIN_BLOCK / 32)) ? warp_sums[lane] : 0.0;
        #pragma unroll
        for (int off = 4; off > 0; off >>= 1)
            vsum += __shfl_xor_sync(0xFFFFFFFFu, vsum, off);
        if (lane == 0)
            atomicAdd(out, (float)vsum);
    }
}

// ---------------------------------------------------------------------------
extern "C" void kernel_launch(void* const* d_in, const int* in_sizes, int n_in,
                              void* d_out, int out_size) {
    const float* Uu   = (const float*)d_in[0];
    const float* rest = (const float*)d_in[1];
    const int4* pv  = (const int4*)d_in[2];
    const int4* pe0 = (const int4*)d_in[3];
    const int4* pe1 = (const int4*)d_in[4];
    float* out = (float*)d_out;

    build_coords_kernel<<<(N_VERTS + 255) / 256, 256>>>(Uu, rest, out);
    barrier_energy_kernel<<<MAIN_GRID, MAIN_BLOCK>>>(pv, pe0, pe1, out);
}

// round 6
// speedup vs baseline: 1.9769x; 1.0122x over previous
#include <cuda_runtime.h>
#include <cstdint>

#define N_VERTS 262144
#define N_PAIRS 8388608
#define DHAT2 0.0025f
#define EPSF 1e-12f

#define MAIN_BLOCK 256
#define MAIN_GRID 2048
// n4 = N_PAIRS/4 = 2097152 = 4 * (MAIN_GRID*MAIN_BLOCK) exactly.

// Scratch: current coordinates (rest + displacement), fits in L2 (2 MB).
__device__ float2 g_coords[N_VERTS];

// ---------------------------------------------------------------------------
// Kernel A: coords = rest + Uu.reshape(-1,2); zero the output scalar.
// float4 loads: two verts per thread, fully coalesced.
// ---------------------------------------------------------------------------
__global__ void build_coords_kernel(const float4* __restrict__ Uu,
                                    const float4* __restrict__ rest,
                                    float* __restrict__ out) {
    int i = blockIdx.x * blockDim.x + threadIdx.x;  // i indexes vert pairs
    if (i < N_VERTS / 2) {
        float4 r = __ldg(&rest[i]);
        float4 u = __ldg(&Uu[i]);
        float4 c = make_float4(r.x + u.x, r.y + u.y, r.z + u.z, r.w + u.w);
        reinterpret_cast<float4*>(g_coords)[i] = c;
    }
    if (blockIdx.x == 0 && threadIdx.x == 0) {
        out[0] = 0.0f;  // d_out is poisoned; initialize
    }
}

// ---------------------------------------------------------------------------
// Per-pair barrier term (reference math, fp32; fast log/div — rel tolerance
// is 1e-3, __logf error ~5e-7).
// ---------------------------------------------------------------------------
__device__ __forceinline__ float pair_barrier(int iv, int ie0, int ie1) {
    float2 p = __ldg(&g_coords[iv]);
    float2 a = __ldg(&g_coords[ie0]);
    float2 b = __ldg(&g_coords[ie1]);

    float abx = b.x - a.x, aby = b.y - a.y;
    float apx = p.x - a.x, apy = p.y - a.y;
    float denom = abx * abx + aby * aby;
    float t = __fdividef(apx * abx + apy * aby, fmaxf(denom, EPSF));
    t = fminf(fmaxf(t, 0.0f), 1.0f);
    float dx = apx - t * abx;
    float dy = apy - t * aby;
    float d2 = dx * dx + dy * dy;

    if (d2 < DHAT2) {
        float d2s = fmaxf(d2, EPSF);
        float m = d2s - DHAT2;
        return -(m * m) * __logf(d2s * (1.0f / DHAT2));
    }
    return 0.0f;
}

__device__ __forceinline__ float group_barrier(int4 v, int4 e0, int4 e1) {
    return pair_barrier(v.x, e0.x, e1.x)
         + pair_barrier(v.y, e0.y, e1.y)
         + pair_barrier(v.z, e0.z, e1.z)
         + pair_barrier(v.w, e0.w, e1.w);
}

// ---------------------------------------------------------------------------
// Kernel B: PDL secondary. Prefetch ALL index data (12 int4 = exactly the
// thread's 16 pairs) while kernel A is still running, then grid-dependency
// sync, then gather+compute. Fully unrolled: no loop, no tail.
// ---------------------------------------------------------------------------
__global__ void __launch_bounds__(MAIN_BLOCK)
barrier_energy_kernel(const int4* __restrict__ pv4,
                      const int4* __restrict__ pe04,
                      const int4* __restrict__ pe14,
                      float* __restrict__ out) {
    const int S = MAIN_GRID * MAIN_BLOCK;  // 524288
    int tid = blockIdx.x * MAIN_BLOCK + threadIdx.x;

    // Phase 1: coalesced index prefetch — independent of kernel A's output.
    int4 v0  = __ldg(&pv4[tid]);
    int4 e00 = __ldg(&pe04[tid]);
    int4 e10 = __ldg(&pe14[tid]);
    int4 v1  = __ldg(&pv4[tid + S]);
    int4 e01 = __ldg(&pe04[tid + S]);
    int4 e11 = __ldg(&pe14[tid + S]);
    int4 v2  = __ldg(&pv4[tid + 2 * S]);
    int4 e02 = __ldg(&pe04[tid + 2 * S]);
    int4 e12 = __ldg(&pe14[tid + 2 * S]);
    int4 v3  = __ldg(&pv4[tid + 3 * S]);
    int4 e03 = __ldg(&pe04[tid + 3 * S]);
    int4 e13 = __ldg(&pe14[tid + 3 * S]);

    // Wait for kernel A (g_coords) to be complete and visible.
    cudaGridDependencySynchronize();

    float s0 = group_barrier(v0, e00, e10);
    float s1 = group_barrier(v1, e01, e11);
    float s2 = group_barrier(v2, e02, e12);
    float s3 = group_barrier(v3, e03, e13);
    double acc = (double)(s0 + s1) + (double)(s2 + s3);

    // Warp reduction
    #pragma unroll
    for (int off = 16; off > 0; off >>= 1)
        acc += __shfl_xor_sync(0xFFFFFFFFu, acc, off);

    __shared__ double warp_sums[MAIN_BLOCK / 32];
    int lane = threadIdx.x & 31;
    int wid = threadIdx.x >> 5;
    if (lane == 0) warp_sums[wid] = acc;
    __syncthreads();

    if (wid == 0) {
        double vsum = (lane < (MAIN_BLOCK / 32)) ? warp_sums[lane] : 0.0;
        #pragma unroll
        for (int off = 4; off > 0; off >>= 1)
            vsum += __shfl_xor_sync(0xFFFFFFFFu, vsum, off);
        if (lane == 0)
            atomicAdd(out, (float)vsum);
    }
}

// ---------------------------------------------------------------------------
extern "C" void kernel_launch(void* const* d_in, const int* in_sizes, int n_in,
                              void* d_out, int out_size) {
    const float4* Uu   = (const float4*)d_in[0];
    const float4* rest = (const float4*)d_in[1];
    const int4* pv  = (const int4*)d_in[2];
    const int4* pe0 = (const int4*)d_in[3];
    const int4* pe1 = (const int4*)d_in[4];
    float* out = (float*)d_out;

    build_coords_kernel<<<(N_VERTS / 2 + 255) / 256, 256>>>(Uu, rest, out);

    // PDL launch: B starts while A runs; B blocks at
    // cudaGridDependencySynchronize() until A completes.
    cudaLaunchAttribute attrs[1];
    attrs[0].id = cudaLaunchAttributeProgrammaticStreamSerialization;
    attrs[0].val.programmaticStreamSerializationAllowed = 1;

    cudaLaunchConfig_t cfg = {};
    cfg.gridDim = dim3(MAIN_GRID, 1, 1);
    cfg.blockDim = dim3(MAIN_BLOCK, 1, 1);
    cfg.dynamicSmemBytes = 0;
    cfg.stream = 0;
    cfg.attrs = attrs;
    cfg.numAttrs = 1;

    cudaLaunchKernelEx(&cfg, barrier_energy_kernel, pv, pe0, pe1, out);
}

// round 7
// speedup vs baseline: 1.9972x; 1.0102x over previous
#include <cuda_runtime.h>
#include <cstdint>

#define N_VERTS 262144
#define N_PAIRS 8388608
#define DHAT2 0.0025f
#define EPSF 1e-12f

#define MAIN_BLOCK 256
#define MAIN_GRID 2048
// n4 = N_PAIRS/4 = 2097152 = 4 * (MAIN_GRID*MAIN_BLOCK) exactly.

// Scratch: current coordinates (rest + displacement), fits in L2 (2 MB).
__device__ float2 g_coords[N_VERTS];

// ---------------------------------------------------------------------------
// Kernel A: coords = rest + Uu.reshape(-1,2); zero the output scalar.
// float4 loads: two verts per thread, fully coalesced. 512-thread blocks to
// minimize block count (shorter tail under PDL overlap).
// ---------------------------------------------------------------------------
__global__ void __launch_bounds__(512)
build_coords_kernel(const float4* __restrict__ Uu,
                    const float4* __restrict__ rest,
                    float* __restrict__ out) {
    int i = blockIdx.x * blockDim.x + threadIdx.x;  // indexes vert pairs
    if (i < N_VERTS / 2) {
        float4 r = __ldg(&rest[i]);
        float4 u = __ldg(&Uu[i]);
        float4 c = make_float4(r.x + u.x, r.y + u.y, r.z + u.z, r.w + u.w);
        reinterpret_cast<float4*>(g_coords)[i] = c;
    }
    if (blockIdx.x == 0 && threadIdx.x == 0) {
        out[0] = 0.0f;  // d_out is poisoned; initialize
    }
}

// ---------------------------------------------------------------------------
// Streaming (evict-first) int4 load: index data is read exactly once; keep it
// out of L1 so the coords table can stay resident there.
// ---------------------------------------------------------------------------
__device__ __forceinline__ int4 ldcs_int4(const int4* p) {
    return __ldcs(p);
}

// ---------------------------------------------------------------------------
// Per-pair barrier term (reference math, fp32; fast log/div — rel tolerance
// is 1e-3, __logf error ~5e-7).
// ---------------------------------------------------------------------------
__device__ __forceinline__ float pair_barrier(int iv, int ie0, int ie1) {
    float2 p = __ldg(&g_coords[iv]);
    float2 a = __ldg(&g_coords[ie0]);
    float2 b = __ldg(&g_coords[ie1]);

    float abx = b.x - a.x, aby = b.y - a.y;
    float apx = p.x - a.x, apy = p.y - a.y;
    float denom = abx * abx + aby * aby;
    float t = __fdividef(apx * abx + apy * aby, fmaxf(denom, EPSF));
    t = fminf(fmaxf(t, 0.0f), 1.0f);
    float dx = apx - t * abx;
    float dy = apy - t * aby;
    float d2 = dx * dx + dy * dy;

    if (d2 < DHAT2) {
        float d2s = fmaxf(d2, EPSF);
        float m = d2s - DHAT2;
        return -(m * m) * __logf(d2s * (1.0f / DHAT2));
    }
    return 0.0f;
}

__device__ __forceinline__ float group_barrier(int4 v, int4 e0, int4 e1) {
    return pair_barrier(v.x, e0.x, e1.x)
         + pair_barrier(v.y, e0.y, e1.y)
         + pair_barrier(v.z, e0.z, e1.z)
         + pair_barrier(v.w, e0.w, e1.w);
}

// ---------------------------------------------------------------------------
// Kernel B: PDL secondary. Prefetch ALL index data (12 int4 = exactly the
// thread's 16 pairs, streaming/evict-first) while kernel A runs, then
// grid-dependency sync, then gather+compute. Fully unrolled: no loop, no tail.
// ---------------------------------------------------------------------------
__global__ void __launch_bounds__(MAIN_BLOCK)
barrier_energy_kernel(const int4* __restrict__ pv4,
                      const int4* __restrict__ pe04,
                      const int4* __restrict__ pe14,
                      float* __restrict__ out) {
    const int S = MAIN_GRID * MAIN_BLOCK;  // 524288
    int tid = blockIdx.x * MAIN_BLOCK + threadIdx.x;

    // Phase 1: coalesced streaming index prefetch — independent of kernel A.
    int4 v0  = ldcs_int4(&pv4[tid]);
    int4 e00 = ldcs_int4(&pe04[tid]);
    int4 e10 = ldcs_int4(&pe14[tid]);
    int4 v1  = ldcs_int4(&pv4[tid + S]);
    int4 e01 = ldcs_int4(&pe04[tid + S]);
    int4 e11 = ldcs_int4(&pe14[tid + S]);
    int4 v2  = ldcs_int4(&pv4[tid + 2 * S]);
    int4 e02 = ldcs_int4(&pe04[tid + 2 * S]);
    int4 e12 = ldcs_int4(&pe14[tid + 2 * S]);
    int4 v3  = ldcs_int4(&pv4[tid + 3 * S]);
    int4 e03 = ldcs_int4(&pe04[tid + 3 * S]);
    int4 e13 = ldcs_int4(&pe14[tid + 3 * S]);

    // Wait for kernel A (g_coords) to be complete and visible.
    cudaGridDependencySynchronize();

    float s0 = group_barrier(v0, e00, e10);
    float s1 = group_barrier(v1, e01, e11);
    float s2 = group_barrier(v2, e02, e12);
    float s3 = group_barrier(v3, e03, e13);
    double acc = (double)(s0 + s1) + (double)(s2 + s3);

    // Warp reduction
    #pragma unroll
    for (int off = 16; off > 0; off >>= 1)
        acc += __shfl_xor_sync(0xFFFFFFFFu, acc, off);

    __shared__ double warp_sums[MAIN_BLOCK / 32];
    int lane = threadIdx.x & 31;
    int wid = threadIdx.x >> 5;
    if (lane == 0) warp_sums[wid] = acc;
    __syncthreads();

    if (wid == 0) {
        double vsum = (lane < (MAIN_BLOCK / 32)) ? warp_sums[lane] : 0.0;
        #pragma unroll
        for (int off = 4; off > 0; off >>= 1)
            vsum += __shfl_xor_sync(0xFFFFFFFFu, vsum, off);
        if (lane == 0)
            atomicAdd(out, (float)vsum);
    }
}

// ---------------------------------------------------------------------------
extern "C" void kernel_launch(void* const* d_in, const int* in_sizes, int n_in,
                              void* d_out, int out_size) {
    const float4* Uu   = (const float4*)d_in[0];
    const float4* rest = (const float4*)d_in[1];
    const int4* pv  = (const int4*)d_in[2];
    const int4* pe0 = (const int4*)d_in[3];
    const int4* pe1 = (const int4*)d_in[4];
    float* out = (float*)d_out;

    build_coords_kernel<<<(N_VERTS / 2 + 511) / 512, 512>>>(Uu, rest, out);

    // PDL launch: B starts while A runs; B blocks at
    // cudaGridDependencySynchronize() until A completes.
    cudaLaunchAttribute attrs[1];
    attrs[0].id = cudaLaunchAttributeProgrammaticStreamSerialization;
    attrs[0].val.programmaticStreamSerializationAllowed = 1;

    cudaLaunchConfig_t cfg = {};
    cfg.gridDim = dim3(MAIN_GRID, 1, 1);
    cfg.blockDim = dim3(MAIN_BLOCK, 1, 1);
    cfg.dynamicSmemBytes = 0;
    cfg.stream = 0;
    cfg.attrs = attrs;
    cfg.numAttrs = 1;

    cudaLaunchKernelEx(&cfg, barrier_energy_kernel, pv, pe0, pe1, out);
}